// round 15
// baseline (speedup 1.0000x reference)
#include <cuda_runtime.h>
#include <cuda_bf16.h>
#include <stdint.h>

#define DIM   64
#define TILE  64      // rows per CTA = 4 warps x 16 rows
#define NT    128
#define NSTEP 2
#define KPAD  72      // Bt row stride in bf16 (conflict-free frag loads)

// pack two floats to bf16x2: e -> low half, o -> high half
static __device__ __forceinline__ uint32_t bf2(float e, float o){
    uint32_t r; asm("cvt.rn.bf16x2.f32 %0, %1, %2;" : "=r"(r) : "f"(o), "f"(e)); return r;
}
static __device__ __forceinline__ float lo_f(uint32_t p){ return __uint_as_float(p << 16); }
static __device__ __forceinline__ float hi_f(uint32_t p){ return __uint_as_float(p & 0xFFFF0000u); }

// smooth_leaky_relu: 0.1*x + 0.9*softplus(x)
static __device__ __forceinline__ float act(float x){
    float sp = fmaxf(x, 0.f) + __logf(1.f + __expf(-fabsf(x)));
    return fmaf(0.9f, sp, 0.1f * x);
}

#define MMA(d, a0, a1, a2, a3, b0v, b1v) \
    asm volatile("mma.sync.aligned.m16n8k16.row.col.f32.bf16.bf16.f32 " \
        "{%0,%1,%2,%3}, {%4,%5,%6,%7}, {%8,%9}, {%0,%1,%2,%3};" \
        : "+f"((d)[0]), "+f"((d)[1]), "+f"((d)[2]), "+f"((d)[3]) \
        : "r"(a0), "r"(a1), "r"(a2), "r"(a3), "r"(b0v), "r"(b1v))

// build A-fragments (hi+lo split) for n-tile j from 4 fp32 values.
// j even -> (a0,a1) of K-chunk j/2 ; j odd -> (a2,a3) of K-chunk j/2
#define PACKJ(j, z0, z1, z2, z3) { \
    uint32_t h0 = bf2(z0, z1), h1 = bf2(z2, z3); \
    ah[(j)>>1][2*((j)&1)]   = h0; \
    ah[(j)>>1][2*((j)&1)+1] = h1; \
    al[(j)>>1][2*((j)&1)]   = bf2((z0) - lo_f(h0), (z1) - hi_f(h0)); \
    al[(j)>>1][2*((j)&1)+1] = bf2((z2) - lo_f(h1), (z3) - hi_f(h1)); }

// D = (t*wt + b) + Z @ Bt^T, 3-pass split: hi*hi + lo*hi + hi*lo.
// dv init from fp32 smem (exact) replaces the former t/bias MMA chunk.
#define GEMM(TT) { \
    _Pragma("unroll") \
    for (int j = 0; j < 8; j++){ \
        float2 wtc = *reinterpret_cast<const float2*>(SWT + 8*j + 2*t4); \
        float2 bc  = *reinterpret_cast<const float2*>(SB  + 8*j + 2*t4); \
        dv[j][0] = fmaf((float)(TT), wtc.x, bc.x); \
        dv[j][1] = fmaf((float)(TT), wtc.y, bc.y); \
        dv[j][2] = dv[j][0]; dv[j][3] = dv[j][1]; \
    } \
    _Pragma("unroll") \
    for (int kc = 0; kc < 4; kc++){ \
        _Pragma("unroll") \
        for (int j = 0; j < 8; j++){ \
            const __nv_bfloat16* bp = BH + (8*j + g)*KPAD + 16*kc + 2*t4; \
            const __nv_bfloat16* lp = BL + (8*j + g)*KPAD + 16*kc + 2*t4; \
            uint32_t b0 = *(const uint32_t*)bp; \
            uint32_t b1 = *(const uint32_t*)(bp + 8); \
            uint32_t c0 = *(const uint32_t*)lp; \
            uint32_t c1 = *(const uint32_t*)(lp + 8); \
            MMA(dv[j], ah[kc][0], ah[kc][1], ah[kc][2], ah[kc][3], b0, b1); \
            MMA(dv[j], al[kc][0], al[kc][1], al[kc][2], al[kc][3], b0, b1); \
            MMA(dv[j], ah[kc][0], ah[kc][1], ah[kc][2], ah[kc][3], c0, c1); \
        } \
    } }

// epilogue: k = act(D); RK accumulate; build next stage input fragments
#define EPI(WACC, FIRST, COEF, FIN, BUILD) { \
    _Pragma("unroll") \
    for (int j = 0; j < 8; j++){ \
        float k0 = act(dv[j][0]), k1 = act(dv[j][1]); \
        float k2 = act(dv[j][2]), k3 = act(dv[j][3]); \
        if (FIRST){ av[j][0]=k0; av[j][1]=k1; av[j][2]=k2; av[j][3]=k3; } \
        else { av[j][0] = fmaf((float)(WACC), k0, av[j][0]); \
               av[j][1] = fmaf((float)(WACC), k1, av[j][1]); \
               av[j][2] = fmaf((float)(WACC), k2, av[j][2]); \
               av[j][3] = fmaf((float)(WACC), k3, av[j][3]); } \
        float z0, z1, z2, z3; \
        if (FIN){ \
            yv[j][0] = fmaf(h6, av[j][0], yv[j][0]); z0 = yv[j][0]; \
            yv[j][1] = fmaf(h6, av[j][1], yv[j][1]); z1 = yv[j][1]; \
            yv[j][2] = fmaf(h6, av[j][2], yv[j][2]); z2 = yv[j][2]; \
            yv[j][3] = fmaf(h6, av[j][3], yv[j][3]); z3 = yv[j][3]; \
        } else { \
            z0 = fmaf((float)(COEF), k0, yv[j][0]); \
            z1 = fmaf((float)(COEF), k1, yv[j][1]); \
            z2 = fmaf((float)(COEF), k2, yv[j][2]); \
            z3 = fmaf((float)(COEF), k3, yv[j][3]); \
        } \
        if (BUILD){ PACKJ(j, z0, z1, z2, z3); } \
    } }

__global__ void __launch_bounds__(NT, 3) ode_mma(
    const float* __restrict__ x, const float* __restrict__ W,
    const float* __restrict__ bias, float* __restrict__ out)
{
    // Bt[n=out-col][k] bf16, hi & lo: k 0..63 = W[n][k+1]
    __shared__ __align__(16) __nv_bfloat16 BH[64 * KPAD];
    __shared__ __align__(16) __nv_bfloat16 BL[64 * KPAD];
    __shared__ __align__(8)  float SWT[64];   // W[n][0] (t coefficient), fp32
    __shared__ __align__(8)  float SB[64];    // bias, fp32

    const int tid  = threadIdx.x;
    const int lane = tid & 31;
    const int wid  = tid >> 5;
    const int g    = lane >> 2;       // mma group id (0..7)
    const int t4   = lane & 3;        // thread-in-group
    const int r0   = blockIdx.x * TILE + wid * 16 + g;   // rows r0, r0+8

    // zero Bt (padding cols must be 0), then scatter W hi/lo + t-coeff/bias
    for (int i = tid; i < 64 * KPAD / 2; i += NT){
        reinterpret_cast<uint32_t*>(BH)[i] = 0;
        reinterpret_cast<uint32_t*>(BL)[i] = 0;
    }
    __syncthreads();
    for (int idx = tid; idx < 64 * 64; idx += NT){
        int c = idx >> 6, q = idx & 63;
        float w = W[c * (DIM + 1) + q + 1];
        __nv_bfloat16 hb = __float2bfloat16(w);
        BH[c * KPAD + q] = hb;
        BL[c * KPAD + q] = __float2bfloat16(w - __bfloat162float(hb));
    }
    if (tid < 64){ SWT[tid] = W[tid * (DIM + 1)]; SB[tid] = bias[tid]; }
    __syncthreads();   // last barrier — warps run free from here

    float yv[8][4], av[8][4], dv[8][4];
    uint32_t ah[4][4], al[4][4];

    // load x into D-layout fragments (rows r0 / r0+8, cols 8j+2t4..+1)
    #pragma unroll
    for (int j = 0; j < 8; j++){
        float2 v0 = *reinterpret_cast<const float2*>(x + (size_t)r0 * DIM + 8*j + 2*t4);
        float2 v1 = *reinterpret_cast<const float2*>(x + (size_t)(r0 + 8) * DIM + 8*j + 2*t4);
        yv[j][0] = v0.x; yv[j][1] = v0.y; yv[j][2] = v1.x; yv[j][3] = v1.y;
    }
    #pragma unroll
    for (int j = 0; j < 8; j++){ PACKJ(j, yv[j][0], yv[j][1], yv[j][2], yv[j][3]); }

    const float hh = 1.0f / NSTEP;
    const float h2 = 0.5f * hh;
    const float h6 = hh * (1.0f / 6.0f);

    #pragma unroll 1
    for (int s = 0; s < NSTEP; s++){
        float t0 = s * hh;
        bool last = (s == NSTEP - 1);
        GEMM(t0);      EPI(1.0f, 1, h2,  0, 1);        // k1
        GEMM(t0 + h2); EPI(2.0f, 0, h2,  0, 1);        // k2
        GEMM(t0 + h2); EPI(2.0f, 0, hh,  0, 1);        // k3
        GEMM(t0 + hh); EPI(1.0f, 0, 0.f, 1, !last);    // k4 + combine
    }

    #pragma unroll
    for (int j = 0; j < 8; j++){
        *reinterpret_cast<float2*>(out + (size_t)r0 * DIM + 8*j + 2*t4)
            = make_float2(yv[j][0], yv[j][1]);
        *reinterpret_cast<float2*>(out + (size_t)(r0 + 8) * DIM + 8*j + 2*t4)
            = make_float2(yv[j][2], yv[j][3]);
    }
}

extern "C" void kernel_launch(void* const* d_in, const int* in_sizes, int n_in,
                              void* d_out, int out_size)
{
    const float* x    = (const float*)d_in[0];
    const float* W    = (const float*)d_in[1];
    const float* bias = (const float*)d_in[2];
    float* out = (float*)d_out;

    int rows   = in_sizes[0] / DIM;     // 262144
    int blocks = rows / TILE;           // 4096

    ode_mma<<<blocks, NT>>>(x, W, bias, out);
}

// round 16
// speedup vs baseline: 1.4431x; 1.4431x over previous
#include <cuda_runtime.h>
#include <cuda_bf16.h>
#include <stdint.h>

#define DIM   64
#define TILE  64      // rows per CTA = 4 warps x 16 rows
#define NT    128
#define NSTEP 2
#define KPAD  72      // Bt row stride in bf16 (conflict-free frag loads)

// pack two floats to bf16x2: e -> low half, o -> high half
static __device__ __forceinline__ uint32_t bf2(float e, float o){
    uint32_t r; asm("cvt.rn.bf16x2.f32 %0, %1, %2;" : "=r"(r) : "f"(o), "f"(e)); return r;
}
static __device__ __forceinline__ float lo_f(uint32_t p){ return __uint_as_float(p << 16); }
static __device__ __forceinline__ float hi_f(uint32_t p){ return __uint_as_float(p & 0xFFFF0000u); }

// smooth_leaky_relu: 0.1*x + 0.9*softplus(x)
static __device__ __forceinline__ float act(float x){
    float sp = fmaxf(x, 0.f) + __logf(1.f + __expf(-fabsf(x)));
    return fmaf(0.9f, sp, 0.1f * x);
}

#define MMA(d, a0, a1, a2, a3, b0v, b1v) \
    asm volatile("mma.sync.aligned.m16n8k16.row.col.f32.bf16.bf16.f32 " \
        "{%0,%1,%2,%3}, {%4,%5,%6,%7}, {%8,%9}, {%0,%1,%2,%3};" \
        : "+f"((d)[0]), "+f"((d)[1]), "+f"((d)[2]), "+f"((d)[3]) \
        : "r"(a0), "r"(a1), "r"(a2), "r"(a3), "r"(b0v), "r"(b1v))

// build A-fragments (hi+lo split) for n-tile j from 4 fp32 values.
// j even -> (a0,a1) of K-chunk j/2 ; j odd -> (a2,a3) of K-chunk j/2
#define PACKJ(j, z0, z1, z2, z3) { \
    uint32_t h0 = bf2(z0, z1), h1 = bf2(z2, z3); \
    ah[(j)>>1][2*((j)&1)]   = h0; \
    ah[(j)>>1][2*((j)&1)+1] = h1; \
    al[(j)>>1][2*((j)&1)]   = bf2((z0) - lo_f(h0), (z1) - hi_f(h0)); \
    al[(j)>>1][2*((j)&1)+1] = bf2((z2) - lo_f(h1), (z3) - hi_f(h1)); }

// D = (t*wt + b) + Z @ Bt^T, 3-pass split: hi*hi + lo*hi + hi*lo.
// dv init from fp32 smem (exact) replaces the former t/bias MMA chunk.
#define GEMM(TT) { \
    _Pragma("unroll") \
    for (int j = 0; j < 8; j++){ \
        float2 wtc = *reinterpret_cast<const float2*>(SWT + 8*j + 2*t4); \
        float2 bc  = *reinterpret_cast<const float2*>(SB  + 8*j + 2*t4); \
        dv[j][0] = fmaf((float)(TT), wtc.x, bc.x); \
        dv[j][1] = fmaf((float)(TT), wtc.y, bc.y); \
        dv[j][2] = dv[j][0]; dv[j][3] = dv[j][1]; \
    } \
    _Pragma("unroll") \
    for (int kc = 0; kc < 4; kc++){ \
        _Pragma("unroll") \
        for (int j = 0; j < 8; j++){ \
            const __nv_bfloat16* bp = BH + (8*j + g)*KPAD + 16*kc + 2*t4; \
            const __nv_bfloat16* lp = BL + (8*j + g)*KPAD + 16*kc + 2*t4; \
            uint32_t b0 = *(const uint32_t*)bp; \
            uint32_t b1 = *(const uint32_t*)(bp + 8); \
            uint32_t c0 = *(const uint32_t*)lp; \
            uint32_t c1 = *(const uint32_t*)(lp + 8); \
            MMA(dv[j], ah[kc][0], ah[kc][1], ah[kc][2], ah[kc][3], b0, b1); \
            MMA(dv[j], al[kc][0], al[kc][1], al[kc][2], al[kc][3], b0, b1); \
            MMA(dv[j], ah[kc][0], ah[kc][1], ah[kc][2], ah[kc][3], c0, c1); \
        } \
    } }

// epilogue: k = act(D); RK accumulate; build next stage input fragments
#define EPI(WACC, FIRST, COEF, FIN, BUILD) { \
    _Pragma("unroll") \
    for (int j = 0; j < 8; j++){ \
        float k0 = act(dv[j][0]), k1 = act(dv[j][1]); \
        float k2 = act(dv[j][2]), k3 = act(dv[j][3]); \
        if (FIRST){ av[j][0]=k0; av[j][1]=k1; av[j][2]=k2; av[j][3]=k3; } \
        else { av[j][0] = fmaf((float)(WACC), k0, av[j][0]); \
               av[j][1] = fmaf((float)(WACC), k1, av[j][1]); \
               av[j][2] = fmaf((float)(WACC), k2, av[j][2]); \
               av[j][3] = fmaf((float)(WACC), k3, av[j][3]); } \
        float z0, z1, z2, z3; \
        if (FIN){ \
            yv[j][0] = fmaf(h6, av[j][0], yv[j][0]); z0 = yv[j][0]; \
            yv[j][1] = fmaf(h6, av[j][1], yv[j][1]); z1 = yv[j][1]; \
            yv[j][2] = fmaf(h6, av[j][2], yv[j][2]); z2 = yv[j][2]; \
            yv[j][3] = fmaf(h6, av[j][3], yv[j][3]); z3 = yv[j][3]; \
        } else { \
            z0 = fmaf((float)(COEF), k0, yv[j][0]); \
            z1 = fmaf((float)(COEF), k1, yv[j][1]); \
            z2 = fmaf((float)(COEF), k2, yv[j][2]); \
            z3 = fmaf((float)(COEF), k3, yv[j][3]); \
        } \
        if (BUILD){ PACKJ(j, z0, z1, z2, z3); } \
    } }

__global__ void __launch_bounds__(NT) ode_mma(
    const float* __restrict__ x, const float* __restrict__ W,
    const float* __restrict__ bias, float* __restrict__ out)
{
    // Bt[n=out-col][k] bf16, hi & lo: k 0..63 = W[n][k+1]
    __shared__ __align__(16) __nv_bfloat16 BH[64 * KPAD];
    __shared__ __align__(16) __nv_bfloat16 BL[64 * KPAD];
    __shared__ __align__(8)  float SWT[64];   // W[n][0] (t coefficient), fp32
    __shared__ __align__(8)  float SB[64];    // bias, fp32

    const int tid  = threadIdx.x;
    const int lane = tid & 31;
    const int wid  = tid >> 5;
    const int g    = lane >> 2;       // mma group id (0..7)
    const int t4   = lane & 3;        // thread-in-group
    const int r0   = blockIdx.x * TILE + wid * 16 + g;   // rows r0, r0+8

    // zero Bt (padding cols must be 0), then scatter W hi/lo + t-coeff/bias
    for (int i = tid; i < 64 * KPAD / 2; i += NT){
        reinterpret_cast<uint32_t*>(BH)[i] = 0;
        reinterpret_cast<uint32_t*>(BL)[i] = 0;
    }
    __syncthreads();
    for (int idx = tid; idx < 64 * 64; idx += NT){
        int c = idx >> 6, q = idx & 63;
        float w = W[c * (DIM + 1) + q + 1];
        __nv_bfloat16 hb = __float2bfloat16(w);
        BH[c * KPAD + q] = hb;
        BL[c * KPAD + q] = __float2bfloat16(w - __bfloat162float(hb));
    }
    if (tid < 64){ SWT[tid] = W[tid * (DIM + 1)]; SB[tid] = bias[tid]; }
    __syncthreads();   // last barrier — warps run free from here

    float yv[8][4], av[8][4], dv[8][4];
    uint32_t ah[4][4], al[4][4];

    // load x into D-layout fragments (rows r0 / r0+8, cols 8j+2t4..+1)
    #pragma unroll
    for (int j = 0; j < 8; j++){
        float2 v0 = *reinterpret_cast<const float2*>(x + (size_t)r0 * DIM + 8*j + 2*t4);
        float2 v1 = *reinterpret_cast<const float2*>(x + (size_t)(r0 + 8) * DIM + 8*j + 2*t4);
        yv[j][0] = v0.x; yv[j][1] = v0.y; yv[j][2] = v1.x; yv[j][3] = v1.y;
    }
    #pragma unroll
    for (int j = 0; j < 8; j++){ PACKJ(j, yv[j][0], yv[j][1], yv[j][2], yv[j][3]); }

    const float hh = 1.0f / NSTEP;
    const float h2 = 0.5f * hh;
    const float h6 = hh * (1.0f / 6.0f);

    #pragma unroll 1
    for (int s = 0; s < NSTEP; s++){
        float t0 = s * hh;
        bool last = (s == NSTEP - 1);
        GEMM(t0);      EPI(1.0f, 1, h2,  0, 1);        // k1
        GEMM(t0 + h2); EPI(2.0f, 0, h2,  0, 1);        // k2
        GEMM(t0 + h2); EPI(2.0f, 0, hh,  0, 1);        // k3
        GEMM(t0 + hh); EPI(1.0f, 0, 0.f, 1, !last);    // k4 + combine
    }

    #pragma unroll
    for (int j = 0; j < 8; j++){
        *reinterpret_cast<float2*>(out + (size_t)r0 * DIM + 8*j + 2*t4)
            = make_float2(yv[j][0], yv[j][1]);
        *reinterpret_cast<float2*>(out + (size_t)(r0 + 8) * DIM + 8*j + 2*t4)
            = make_float2(yv[j][2], yv[j][3]);
    }
}

extern "C" void kernel_launch(void* const* d_in, const int* in_sizes, int n_in,
                              void* d_out, int out_size)
{
    const float* x    = (const float*)d_in[0];
    const float* W    = (const float*)d_in[1];
    const float* bias = (const float*)d_in[2];
    float* out = (float*)d_out;

    int rows   = in_sizes[0] / DIM;     // 262144
    int blocks = rows / TILE;           // 4096

    ode_mma<<<blocks, NT>>>(x, W, bias, out);
}